// round 4
// baseline (speedup 1.0000x reference)
#include <cuda_runtime.h>
#include <cuda_fp16.h>
#include <cuda_bf16.h>

#define NN 100000
#define NE 800000
#define DM 128

typedef unsigned long long u64;

// ---------------- scratch (device globals: no cudaMalloc allowed) ----------------
__device__ float  g_deg[NN];
__device__ float  g_dis[NN];
__device__ int    g_cnt[NN];
__device__ int    g_off[NN + 1];
__device__ int    g_cur[NN];
__device__ int    g_src[2 * NE];
__device__ float  g_w[2 * NE];
__device__ float  g_agg[(size_t)NN * DM];
__device__ float  g_buf1[(size_t)NN * DM];
__device__ __half g_xh[(size_t)NN * DM];

#define SCB 256
#define SNB ((NN + SCB - 1) / SCB)   // 391 scan blocks
__device__ int g_bsum[SNB];
__device__ int g_boff[SNB];

// ---------------- build kernels ----------------
__global__ void k_zero() {
    int i = blockIdx.x * blockDim.x + threadIdx.x;
    if (i < NN) { g_deg[i] = 0.f; g_cnt[i] = 0; }
}

__global__ void k_deg(const int* __restrict__ s, const int* __restrict__ r,
                      const float* __restrict__ e) {
    int i = blockIdx.x * blockDim.x + threadIdx.x;
    if (i < NE) {
        int a = s[i], b = r[i];
        float ev = e[i];
        atomicAdd(&g_deg[a], ev);
        atomicAdd(&g_deg[b], ev);
        atomicAdd(&g_cnt[a], 1);
        atomicAdd(&g_cnt[b], 1);
    }
}

__global__ void k_dis() {
    int i = blockIdx.x * blockDim.x + threadIdx.x;
    if (i < NN) {
        float d = g_deg[i];
        g_dis[i] = (d > 0.f) ? rsqrtf(d) : 0.f;
    }
}

// ---------------- parallel 3-phase scan ----------------
__global__ void k_scan1() {
    __shared__ int sh[SCB];
    int i = blockIdx.x * SCB + threadIdx.x;
    int v = (i < NN) ? g_cnt[i] : 0;
    sh[threadIdx.x] = v;
    __syncthreads();
    for (int d = SCB / 2; d > 0; d >>= 1) {
        if (threadIdx.x < d) sh[threadIdx.x] += sh[threadIdx.x + d];
        __syncthreads();
    }
    if (threadIdx.x == 0) g_bsum[blockIdx.x] = sh[0];
}

__global__ void k_scan2() {
    __shared__ int sh[512];
    int t = threadIdx.x;
    int v = (t < SNB) ? g_bsum[t] : 0;
    sh[t] = v;
    __syncthreads();
    for (int d = 1; d < 512; d <<= 1) {
        int x = 0;
        if (t >= d) x = sh[t - d];
        __syncthreads();
        sh[t] += x;
        __syncthreads();
    }
    if (t < SNB) g_boff[t] = sh[t] - v;        // exclusive
    if (t == SNB - 1) g_off[NN] = sh[t];       // total
}

__global__ void k_scan3() {
    __shared__ int sh[SCB];
    int i = blockIdx.x * SCB + threadIdx.x;
    int t = threadIdx.x;
    int v = (i < NN) ? g_cnt[i] : 0;
    sh[t] = v;
    __syncthreads();
    for (int d = 1; d < SCB; d <<= 1) {
        int x = 0;
        if (t >= d) x = sh[t - d];
        __syncthreads();
        sh[t] += x;
        __syncthreads();
    }
    if (i < NN) {
        int excl = sh[t] - v + g_boff[blockIdx.x];
        g_off[i] = excl;
        g_cur[i] = excl;
    }
}

__global__ void k_fill(const int* __restrict__ s, const int* __restrict__ r,
                       const float* __restrict__ e) {
    int i = blockIdx.x * blockDim.x + threadIdx.x;
    if (i < NE) {
        int a = s[i], b = r[i];
        float w = g_dis[a] * e[i] * g_dis[b];  // symmetric for both directions
        int p = atomicAdd(&g_cur[b], 1);       // edge a->b aggregated at b
        g_src[p] = a; g_w[p] = w;
        int q = atomicAdd(&g_cur[a], 1);       // edge b->a aggregated at a
        g_src[q] = b; g_w[q] = w;
    }
}

// ---------------- fp32 -> fp16 convert (for low-traffic gather) ----------------
__global__ void k_cvt(const float* __restrict__ x) {
    int i = blockIdx.x * blockDim.x + threadIdx.x;   // one float4 / thread
    const int N4 = NN * DM / 4;                      // 3.2M
    if (i < N4) {
        float4 v = __ldg(&((const float4*)x)[i]);
        __half2 h0 = __floats2half2_rn(v.x, v.y);
        __half2 h1 = __floats2half2_rn(v.z, v.w);
        ((__half2*)g_xh)[2 * i]     = h0;
        ((__half2*)g_xh)[2 * i + 1] = h1;
    }
}

// ---------------- aggregation: one warp per node, fp16 gather, fp32 acc ----------
__global__ void k_agg() {
    int warp = (blockIdx.x * blockDim.x + threadIdx.x) >> 5;
    int lane = threadIdx.x & 31;
    if (warp >= NN) return;
    int beg = g_off[warp], end = g_off[warp + 1];
    float4 acc = make_float4(0.f, 0.f, 0.f, 0.f);
    // each lane owns halves [lane*4, lane*4+4) of the 128-wide row = one uint2
    // row = 128 halves = 32 uint2  ->  row stride in uint2 is 32
    const uint2* __restrict__ xh2 = (const uint2*)g_xh;
    for (int j = beg; j < end; j++) {
        int src = g_src[j];
        float w = g_w[j];
        uint2 u = __ldg(&xh2[(size_t)src * 32 + lane]);
        __half2 h0 = *(__half2*)&u.x;
        __half2 h1 = *(__half2*)&u.y;
        float2 f0 = __half22float2(h0);
        float2 f1 = __half22float2(h1);
        acc.x = fmaf(w, f0.x, acc.x);
        acc.y = fmaf(w, f0.y, acc.y);
        acc.z = fmaf(w, f1.x, acc.z);
        acc.w = fmaf(w, f1.y, acc.w);
    }
    ((float4*)g_agg)[(size_t)warp * 32 + lane] = acc;
}

// ---------------- fused GEMM + bias + residual, packed fp32x2 FMA ----------------
// out[m,:] = res[m,:] + g_agg[m,:] @ W + b
// Optionally also writes fp16 copy of out (fuses next layer's k_cvt).
// 128x128 tile / block, 256 threads, 8x8 micro-tile, acc packed along K.
#define SW 132   // smem row stride (floats): 132*4B = 528B, 16B-aligned, conflict-min

__device__ __forceinline__ u64 fma2(u64 a, u64 b, u64 c) {
    u64 d;
    asm("fma.rn.f32x2 %0, %1, %2, %3;" : "=l"(d) : "l"(a), "l"(b), "l"(c));
    return d;
}

__global__ void __launch_bounds__(256)
k_gemm(const float* __restrict__ Wm, const float* __restrict__ bias,
       const float* __restrict__ res, float* __restrict__ out,
       int write_half) {
    extern __shared__ float sh[];
    float* As = sh;                 // [128][SW], row-major (k contiguous)
    float* Wt = sh + 128 * SW;      // [128][SW], TRANSPOSED: Wt[j*SW + k] = W[k][j]

    int tid = threadIdx.x;
    int rowBase = blockIdx.x * 128;

    // load + transpose W into smem
    const float4* W4 = (const float4*)Wm;
#pragma unroll
    for (int i = 0; i < 16; i++) {
        int f = tid + i * 256;      // float4 id 0..4095
        int k = f >> 5;             // W row (k index)
        int j0 = (f & 31) * 4;      // W col
        float4 v = __ldg(&W4[f]);
        Wt[(j0 + 0) * SW + k] = v.x;
        Wt[(j0 + 1) * SW + k] = v.y;
        Wt[(j0 + 2) * SW + k] = v.z;
        Wt[(j0 + 3) * SW + k] = v.w;
    }

    // load A tile
    const float4* A4 = (const float4*)g_agg;
#pragma unroll
    for (int i = 0; i < 16; i++) {
        int f = tid + i * 256;
        int row = f >> 5;
        int kq = f & 31;
        int grow = rowBase + row;
        float4 v = make_float4(0.f, 0.f, 0.f, 0.f);
        if (grow < NN) v = __ldg(&A4[(size_t)grow * 32 + kq]);
        *((float4*)&As[row * SW + kq * 4]) = v;
    }
    __syncthreads();

    int tx = tid & 15, ty = tid >> 4;
    int r0 = ty * 8;                // 8 rows per thread
    // 8 columns per thread: c = tx + 16*m  (bank-conflict-friendly for Wt reads)

    u64 acc[8][8];
#pragma unroll
    for (int i = 0; i < 8; i++)
#pragma unroll
        for (int m = 0; m < 8; m++) acc[i][m] = 0ull;

#pragma unroll 2
    for (int k = 0; k < 128; k += 4) {
        ulonglong2 a4[8], w4[8];
#pragma unroll
        for (int i = 0; i < 8; i++)
            a4[i] = *((const ulonglong2*)&As[(r0 + i) * SW + k]);
#pragma unroll
        for (int m = 0; m < 8; m++)
            w4[m] = *((const ulonglong2*)&Wt[(tx + 16 * m) * SW + k]);
#pragma unroll
        for (int i = 0; i < 8; i++)
#pragma unroll
            for (int m = 0; m < 8; m++) {
                acc[i][m] = fma2(a4[i].x, w4[m].x, acc[i][m]);
                acc[i][m] = fma2(a4[i].y, w4[m].y, acc[i][m]);
            }
    }

    // epilogue: reduce packed pair, + residual + bias (+ optional fp16 copy)
    float bv[8];
#pragma unroll
    for (int m = 0; m < 8; m++) bv[m] = __ldg(&bias[tx + 16 * m]);

#pragma unroll
    for (int i = 0; i < 8; i++) {
        int grow = rowBase + r0 + i;
        if (grow < NN) {
            const float* rp = &res[(size_t)grow * DM];
            float* op = &out[(size_t)grow * DM];
            __half* hp = &g_xh[(size_t)grow * DM];
#pragma unroll
            for (int m = 0; m < 8; m++) {
                int c = tx + 16 * m;
                float2 p = *((float2*)&acc[i][m]);
                float o = __ldg(&rp[c]) + p.x + p.y + bv[m];
                op[c] = o;
                if (write_half) hp[c] = __float2half_rn(o);
            }
        }
    }
}

// ---------------- launch ----------------
extern "C" void kernel_launch(void* const* d_in, const int* in_sizes, int n_in,
                              void* d_out, int out_size) {
    const float* nodes     = (const float*)d_in[0];
    const int*   senders   = (const int*)d_in[1];
    const int*   receivers = (const int*)d_in[2];
    const float* edges     = (const float*)d_in[3];
    const float* W1 = (const float*)d_in[4];
    const float* b1 = (const float*)d_in[5];
    const float* W2 = (const float*)d_in[6];
    const float* b2 = (const float*)d_in[7];
    float* out = (float*)d_out;

    float* buf1 = nullptr;
    cudaGetSymbolAddress((void**)&buf1, g_buf1);

    const size_t SMEM_GEMM = (size_t)(2 * 128 * SW) * sizeof(float);  // 132 KB
    cudaFuncSetAttribute(k_gemm, cudaFuncAttributeMaxDynamicSharedMemorySize,
                         (int)SMEM_GEMM);

    const int T = 256;
    // CSR + degree build (shared by both layers)
    k_zero<<<(NN + T - 1) / T, T>>>();
    k_deg<<<(NE + T - 1) / T, T>>>(senders, receivers, edges);
    k_dis<<<(NN + T - 1) / T, T>>>();
    k_scan1<<<SNB, SCB>>>();
    k_scan2<<<1, 512>>>();
    k_scan3<<<SNB, SCB>>>();
    k_fill<<<(NE + T - 1) / T, T>>>(senders, receivers, edges);

    const int AGG_GRID  = (NN * 32 + T - 1) / T;       // one warp per node
    const int GEMM_GRID = (NN + 127) / 128;
    const int CVT_GRID  = (NN * DM / 4 + T - 1) / T;   // one float4 per thread

    // layer 1: nodes -> buf1 (gemm also emits fp16 buf1 for layer-2 gather)
    k_cvt<<<CVT_GRID, T>>>(nodes);
    k_agg<<<AGG_GRID, T>>>();
    k_gemm<<<GEMM_GRID, T, SMEM_GEMM>>>(W1, b1, nodes, buf1, 1);

    // layer 2: buf1 -> out
    k_agg<<<AGG_GRID, T>>>();
    k_gemm<<<GEMM_GRID, T, SMEM_GEMM>>>(W2, b2, buf1, out, 0);
}

// round 5
// speedup vs baseline: 1.0106x; 1.0106x over previous
#include <cuda_runtime.h>
#include <cuda_fp16.h>
#include <cuda_bf16.h>

#define NN 100000
#define NE 800000
#define DM 128

typedef unsigned long long u64;

// ---------------- scratch (device globals: no cudaMalloc allowed) ----------------
__device__ float  g_deg[NN];
__device__ float  g_dis[NN];
__device__ int    g_cnt[NN];
__device__ int    g_off[NN + 1];
__device__ int    g_cur[NN];
__device__ int    g_src[2 * NE];
__device__ float  g_w[2 * NE];
__device__ float  g_agg[(size_t)NN * DM];
__device__ float  g_buf1[(size_t)NN * DM];
__device__ __half g_xh[(size_t)NN * DM];

#define SCB 256
#define SNB ((NN + SCB - 1) / SCB)   // 391 scan blocks
__device__ int g_bsum[SNB];
__device__ int g_boff[SNB];

// ---------------- build kernels ----------------
__global__ void k_zero() {
    int i = blockIdx.x * blockDim.x + threadIdx.x;
    if (i < NN) { g_deg[i] = 0.f; g_cnt[i] = 0; }
}

__global__ void k_deg(const int* __restrict__ s, const int* __restrict__ r,
                      const float* __restrict__ e) {
    int i = blockIdx.x * blockDim.x + threadIdx.x;
    if (i < NE) {
        int a = s[i], b = r[i];
        float ev = e[i];
        atomicAdd(&g_deg[a], ev);
        atomicAdd(&g_deg[b], ev);
        atomicAdd(&g_cnt[a], 1);
        atomicAdd(&g_cnt[b], 1);
    }
}

__global__ void k_dis() {
    int i = blockIdx.x * blockDim.x + threadIdx.x;
    if (i < NN) {
        float d = g_deg[i];
        g_dis[i] = (d > 0.f) ? rsqrtf(d) : 0.f;
    }
}

// ---------------- parallel 3-phase scan ----------------
__global__ void k_scan1() {
    __shared__ int sh[SCB];
    int i = blockIdx.x * SCB + threadIdx.x;
    int v = (i < NN) ? g_cnt[i] : 0;
    sh[threadIdx.x] = v;
    __syncthreads();
    for (int d = SCB / 2; d > 0; d >>= 1) {
        if (threadIdx.x < d) sh[threadIdx.x] += sh[threadIdx.x + d];
        __syncthreads();
    }
    if (threadIdx.x == 0) g_bsum[blockIdx.x] = sh[0];
}

__global__ void k_scan2() {
    __shared__ int sh[512];
    int t = threadIdx.x;
    int v = (t < SNB) ? g_bsum[t] : 0;
    sh[t] = v;
    __syncthreads();
    for (int d = 1; d < 512; d <<= 1) {
        int x = 0;
        if (t >= d) x = sh[t - d];
        __syncthreads();
        sh[t] += x;
        __syncthreads();
    }
    if (t < SNB) g_boff[t] = sh[t] - v;        // exclusive
    if (t == SNB - 1) g_off[NN] = sh[t];       // total
}

__global__ void k_scan3() {
    __shared__ int sh[SCB];
    int i = blockIdx.x * SCB + threadIdx.x;
    int t = threadIdx.x;
    int v = (i < NN) ? g_cnt[i] : 0;
    sh[t] = v;
    __syncthreads();
    for (int d = 1; d < SCB; d <<= 1) {
        int x = 0;
        if (t >= d) x = sh[t - d];
        __syncthreads();
        sh[t] += x;
        __syncthreads();
    }
    if (i < NN) {
        int excl = sh[t] - v + g_boff[blockIdx.x];
        g_off[i] = excl;
        g_cur[i] = excl;
    }
}

__global__ void k_fill(const int* __restrict__ s, const int* __restrict__ r,
                       const float* __restrict__ e) {
    int i = blockIdx.x * blockDim.x + threadIdx.x;
    if (i < NE) {
        int a = s[i], b = r[i];
        float w = g_dis[a] * e[i] * g_dis[b];  // symmetric for both directions
        int p = atomicAdd(&g_cur[b], 1);       // edge a->b aggregated at b
        g_src[p] = a; g_w[p] = w;
        int q = atomicAdd(&g_cur[a], 1);       // edge b->a aggregated at a
        g_src[q] = b; g_w[q] = w;
    }
}

// ---------------- fp32 -> fp16 convert (for low-traffic gather) ----------------
__global__ void k_cvt(const float* __restrict__ x) {
    int i = blockIdx.x * blockDim.x + threadIdx.x;   // one float4 / thread
    const int N4 = NN * DM / 4;                      // 3.2M
    if (i < N4) {
        float4 v = __ldg(&((const float4*)x)[i]);
        __half2 h0 = __floats2half2_rn(v.x, v.y);
        __half2 h1 = __floats2half2_rn(v.z, v.w);
        ((__half2*)g_xh)[2 * i]     = h0;
        ((__half2*)g_xh)[2 * i + 1] = h1;
    }
}

// ---------------- aggregation: one warp per node, fp16 gather, MLP=4 batches ----
__device__ __forceinline__ void acc_edge(float4& acc, float w, uint2 u) {
    __half2 h0 = *(__half2*)&u.x;
    __half2 h1 = *(__half2*)&u.y;
    float2 f0 = __half22float2(h0);
    float2 f1 = __half22float2(h1);
    acc.x = fmaf(w, f0.x, acc.x);
    acc.y = fmaf(w, f0.y, acc.y);
    acc.z = fmaf(w, f1.x, acc.z);
    acc.w = fmaf(w, f1.y, acc.w);
}

__global__ void k_agg() {
    int warp = (blockIdx.x * blockDim.x + threadIdx.x) >> 5;
    int lane = threadIdx.x & 31;
    if (warp >= NN) return;
    int beg = g_off[warp], end = g_off[warp + 1];
    float4 acc = make_float4(0.f, 0.f, 0.f, 0.f);
    // lane owns halves [4*lane, 4*lane+4) = one uint2; row stride = 32 uint2
    const uint2* __restrict__ xh2 = (const uint2*)g_xh;

    int j = beg;
    // 4 edges per iteration -> 4 independent gathers in flight (MLP>=4)
    for (; j + 4 <= end; j += 4) {
        int s0 = __ldg(&g_src[j + 0]);
        int s1 = __ldg(&g_src[j + 1]);
        int s2 = __ldg(&g_src[j + 2]);
        int s3 = __ldg(&g_src[j + 3]);
        float w0 = __ldg(&g_w[j + 0]);
        float w1 = __ldg(&g_w[j + 1]);
        float w2 = __ldg(&g_w[j + 2]);
        float w3 = __ldg(&g_w[j + 3]);
        uint2 u0 = __ldg(&xh2[(size_t)s0 * 32 + lane]);
        uint2 u1 = __ldg(&xh2[(size_t)s1 * 32 + lane]);
        uint2 u2 = __ldg(&xh2[(size_t)s2 * 32 + lane]);
        uint2 u3 = __ldg(&xh2[(size_t)s3 * 32 + lane]);
        acc_edge(acc, w0, u0);
        acc_edge(acc, w1, u1);
        acc_edge(acc, w2, u2);
        acc_edge(acc, w3, u3);
    }
    // remainder (<=3): still issue all gathers before accumulating
    {
        int rem = end - j;
        int s0 = 0, s1 = 0, s2 = 0;
        float w0 = 0.f, w1 = 0.f, w2 = 0.f;
        if (rem > 0) { s0 = __ldg(&g_src[j + 0]); w0 = __ldg(&g_w[j + 0]); }
        if (rem > 1) { s1 = __ldg(&g_src[j + 1]); w1 = __ldg(&g_w[j + 1]); }
        if (rem > 2) { s2 = __ldg(&g_src[j + 2]); w2 = __ldg(&g_w[j + 2]); }
        uint2 z = make_uint2(0u, 0u);
        uint2 u0 = (rem > 0) ? __ldg(&xh2[(size_t)s0 * 32 + lane]) : z;
        uint2 u1 = (rem > 1) ? __ldg(&xh2[(size_t)s1 * 32 + lane]) : z;
        uint2 u2 = (rem > 2) ? __ldg(&xh2[(size_t)s2 * 32 + lane]) : z;
        acc_edge(acc, w0, u0);
        acc_edge(acc, w1, u1);
        acc_edge(acc, w2, u2);
    }
    ((float4*)g_agg)[(size_t)warp * 32 + lane] = acc;
}

// ---------------- fused GEMM + bias + residual, packed fp32x2 FMA ----------------
// out[m,:] = res[m,:] + g_agg[m,:] @ W + b
// Optionally also writes fp16 copy of out (fuses next layer's k_cvt).
// 128x128 tile / block, 256 threads, 8x8 micro-tile, acc packed along K.
#define SW 132   // smem row stride (floats): 132*4B = 528B, 16B-aligned, conflict-min

__device__ __forceinline__ u64 fma2(u64 a, u64 b, u64 c) {
    u64 d;
    asm("fma.rn.f32x2 %0, %1, %2, %3;" : "=l"(d) : "l"(a), "l"(b), "l"(c));
    return d;
}

__global__ void __launch_bounds__(256)
k_gemm(const float* __restrict__ Wm, const float* __restrict__ bias,
       const float* __restrict__ res, float* __restrict__ out,
       int write_half) {
    extern __shared__ float sh[];
    float* As = sh;                 // [128][SW], row-major (k contiguous)
    float* Wt = sh + 128 * SW;      // [128][SW], TRANSPOSED: Wt[j*SW + k] = W[k][j]

    int tid = threadIdx.x;
    int rowBase = blockIdx.x * 128;

    // load + transpose W into smem
    const float4* W4 = (const float4*)Wm;
#pragma unroll
    for (int i = 0; i < 16; i++) {
        int f = tid + i * 256;      // float4 id 0..4095
        int k = f >> 5;             // W row (k index)
        int j0 = (f & 31) * 4;      // W col
        float4 v = __ldg(&W4[f]);
        Wt[(j0 + 0) * SW + k] = v.x;
        Wt[(j0 + 1) * SW + k] = v.y;
        Wt[(j0 + 2) * SW + k] = v.z;
        Wt[(j0 + 3) * SW + k] = v.w;
    }

    // load A tile
    const float4* A4 = (const float4*)g_agg;
#pragma unroll
    for (int i = 0; i < 16; i++) {
        int f = tid + i * 256;
        int row = f >> 5;
        int kq = f & 31;
        int grow = rowBase + row;
        float4 v = make_float4(0.f, 0.f, 0.f, 0.f);
        if (grow < NN) v = __ldg(&A4[(size_t)grow * 32 + kq]);
        *((float4*)&As[row * SW + kq * 4]) = v;
    }
    __syncthreads();

    int tx = tid & 15, ty = tid >> 4;
    int r0 = ty * 8;                // 8 rows per thread
    // 8 columns per thread: c = tx + 16*m  (bank-conflict-friendly for Wt reads)

    u64 acc[8][8];
#pragma unroll
    for (int i = 0; i < 8; i++)
#pragma unroll
        for (int m = 0; m < 8; m++) acc[i][m] = 0ull;

#pragma unroll 2
    for (int k = 0; k < 128; k += 4) {
        ulonglong2 a4[8], w4[8];
#pragma unroll
        for (int i = 0; i < 8; i++)
            a4[i] = *((const ulonglong2*)&As[(r0 + i) * SW + k]);
#pragma unroll
        for (int m = 0; m < 8; m++)
            w4[m] = *((const ulonglong2*)&Wt[(tx + 16 * m) * SW + k]);
#pragma unroll
        for (int i = 0; i < 8; i++)
#pragma unroll
            for (int m = 0; m < 8; m++) {
                acc[i][m] = fma2(a4[i].x, w4[m].x, acc[i][m]);
                acc[i][m] = fma2(a4[i].y, w4[m].y, acc[i][m]);
            }
    }

    // epilogue: reduce packed pair, + residual + bias (+ optional fp16 copy)
    float bv[8];
#pragma unroll
    for (int m = 0; m < 8; m++) bv[m] = __ldg(&bias[tx + 16 * m]);

#pragma unroll
    for (int i = 0; i < 8; i++) {
        int grow = rowBase + r0 + i;
        if (grow < NN) {
            const float* rp = &res[(size_t)grow * DM];
            float* op = &out[(size_t)grow * DM];
            __half* hp = &g_xh[(size_t)grow * DM];
#pragma unroll
            for (int m = 0; m < 8; m++) {
                int c = tx + 16 * m;
                float2 p = *((float2*)&acc[i][m]);
                float o = __ldg(&rp[c]) + p.x + p.y + bv[m];
                op[c] = o;
                if (write_half) hp[c] = __float2half_rn(o);
            }
        }
    }
}

// ---------------- launch ----------------
extern "C" void kernel_launch(void* const* d_in, const int* in_sizes, int n_in,
                              void* d_out, int out_size) {
    const float* nodes     = (const float*)d_in[0];
    const int*   senders   = (const int*)d_in[1];
    const int*   receivers = (const int*)d_in[2];
    const float* edges     = (const float*)d_in[3];
    const float* W1 = (const float*)d_in[4];
    const float* b1 = (const float*)d_in[5];
    const float* W2 = (const float*)d_in[6];
    const float* b2 = (const float*)d_in[7];
    float* out = (float*)d_out;

    float* buf1 = nullptr;
    cudaGetSymbolAddress((void**)&buf1, g_buf1);

    const size_t SMEM_GEMM = (size_t)(2 * 128 * SW) * sizeof(float);  // 132 KB
    cudaFuncSetAttribute(k_gemm, cudaFuncAttributeMaxDynamicSharedMemorySize,
                         (int)SMEM_GEMM);

    const int T = 256;
    // CSR + degree build (shared by both layers)
    k_zero<<<(NN + T - 1) / T, T>>>();
    k_deg<<<(NE + T - 1) / T, T>>>(senders, receivers, edges);
    k_dis<<<(NN + T - 1) / T, T>>>();
    k_scan1<<<SNB, SCB>>>();
    k_scan2<<<1, 512>>>();
    k_scan3<<<SNB, SCB>>>();
    k_fill<<<(NE + T - 1) / T, T>>>(senders, receivers, edges);

    const int AGG_GRID  = (NN * 32 + T - 1) / T;       // one warp per node
    const int GEMM_GRID = (NN + 127) / 128;
    const int CVT_GRID  = (NN * DM / 4 + T - 1) / T;   // one float4 per thread

    // layer 1: nodes -> buf1 (gemm also emits fp16 buf1 for layer-2 gather)
    k_cvt<<<CVT_GRID, T>>>(nodes);
    k_agg<<<AGG_GRID, T>>>();
    k_gemm<<<GEMM_GRID, T, SMEM_GEMM>>>(W1, b1, nodes, buf1, 1);

    // layer 2: buf1 -> out
    k_agg<<<AGG_GRID, T>>>();
    k_gemm<<<GEMM_GRID, T, SMEM_GEMM>>>(W2, b2, buf1, out, 0);
}

// round 8
// speedup vs baseline: 1.8093x; 1.7903x over previous
#include <cuda_runtime.h>
#include <cuda_fp16.h>
#include <cuda_bf16.h>
#include <cstdint>
#include <cstring>

#define NN 100000
#define NE 800000
#define DM 128

typedef unsigned long long u64;

__device__ __forceinline__ uint32_t smem_to_u32(const void* p) {
    uint32_t a;
    asm("{ .reg .u64 t; cvta.to.shared.u64 t, %1; cvt.u32.u64 %0, t; }" : "=r"(a) : "l"(p));
    return a;
}
__device__ __forceinline__ uint32_t h2_to_u32(__half2 h) {
    uint32_t u;
    memcpy(&u, &h, 4);
    return u;
}
__device__ __forceinline__ void ldsm4(uint32_t* r, uint32_t addr) {
    asm volatile("ldmatrix.sync.aligned.m8n8.x4.shared.b16 {%0,%1,%2,%3}, [%4];"
        : "=r"(r[0]), "=r"(r[1]), "=r"(r[2]), "=r"(r[3]) : "r"(addr));
}
__device__ __forceinline__ void mma16816(float* c, const uint32_t* a, const uint32_t* b) {
    asm volatile(
        "mma.sync.aligned.m16n8k16.row.col.f32.f16.f16.f32 "
        "{%0,%1,%2,%3}, {%4,%5,%6,%7}, {%8,%9}, {%0,%1,%2,%3};"
        : "+f"(c[0]), "+f"(c[1]), "+f"(c[2]), "+f"(c[3])
        : "r"(a[0]), "r"(a[1]), "r"(a[2]), "r"(a[3]), "r"(b[0]), "r"(b[1]));
}

// ---------------- scratch (device globals: no cudaMalloc allowed) ----------------
__device__ float  g_deg[NN];
__device__ float  g_dis[NN];
__device__ int    g_cnt[NN];
__device__ int    g_off[NN + 1];
__device__ int    g_cur[NN];
__device__ int    g_src[2 * NE];
__device__ float  g_w[2 * NE];
__device__ __half g_aggh[(size_t)NN * DM];   // aggregation result, fp16 (A of GEMM)
__device__ float  g_buf1[(size_t)NN * DM];
__device__ __half g_xh[(size_t)NN * DM];     // node features fp16 (gather table)
__device__ __half g_wt[DM * DM];             // W^T fp16, [n][k] row-major

#define SCB 256
#define SNB ((NN + SCB - 1) / SCB)   // 391 scan blocks
__device__ int g_bsum[SNB];
__device__ int g_boff[SNB];

// ---------------- build kernels ----------------
__global__ void k_zero() {
    int i = blockIdx.x * blockDim.x + threadIdx.x;
    if (i < NN) { g_deg[i] = 0.f; g_cnt[i] = 0; }
}

__global__ void k_deg(const int* __restrict__ s, const int* __restrict__ r,
                      const float* __restrict__ e) {
    int i = blockIdx.x * blockDim.x + threadIdx.x;
    if (i < NE) {
        int a = s[i], b = r[i];
        float ev = e[i];
        atomicAdd(&g_deg[a], ev);
        atomicAdd(&g_deg[b], ev);
        atomicAdd(&g_cnt[a], 1);
        atomicAdd(&g_cnt[b], 1);
    }
}

__global__ void k_dis() {
    int i = blockIdx.x * blockDim.x + threadIdx.x;
    if (i < NN) {
        float d = g_deg[i];
        g_dis[i] = (d > 0.f) ? rsqrtf(d) : 0.f;
    }
}

__global__ void k_scan1() {
    __shared__ int sh[SCB];
    int i = blockIdx.x * SCB + threadIdx.x;
    int v = (i < NN) ? g_cnt[i] : 0;
    sh[threadIdx.x] = v;
    __syncthreads();
    for (int d = SCB / 2; d > 0; d >>= 1) {
        if (threadIdx.x < d) sh[threadIdx.x] += sh[threadIdx.x + d];
        __syncthreads();
    }
    if (threadIdx.x == 0) g_bsum[blockIdx.x] = sh[0];
}

__global__ void k_scan2() {
    __shared__ int sh[512];
    int t = threadIdx.x;
    int v = (t < SNB) ? g_bsum[t] : 0;
    sh[t] = v;
    __syncthreads();
    for (int d = 1; d < 512; d <<= 1) {
        int x = 0;
        if (t >= d) x = sh[t - d];
        __syncthreads();
        sh[t] += x;
        __syncthreads();
    }
    if (t < SNB) g_boff[t] = sh[t] - v;
    if (t == SNB - 1) g_off[NN] = sh[t];
}

__global__ void k_scan3() {
    __shared__ int sh[SCB];
    int i = blockIdx.x * SCB + threadIdx.x;
    int t = threadIdx.x;
    int v = (i < NN) ? g_cnt[i] : 0;
    sh[t] = v;
    __syncthreads();
    for (int d = 1; d < SCB; d <<= 1) {
        int x = 0;
        if (t >= d) x = sh[t - d];
        __syncthreads();
        sh[t] += x;
        __syncthreads();
    }
    if (i < NN) {
        int excl = sh[t] - v + g_boff[blockIdx.x];
        g_off[i] = excl;
        g_cur[i] = excl;
    }
}

__global__ void k_fill(const int* __restrict__ s, const int* __restrict__ r,
                       const float* __restrict__ e) {
    int i = blockIdx.x * blockDim.x + threadIdx.x;
    if (i < NE) {
        int a = s[i], b = r[i];
        float w = g_dis[a] * e[i] * g_dis[b];
        int p = atomicAdd(&g_cur[b], 1);
        g_src[p] = a; g_w[p] = w;
        int q = atomicAdd(&g_cur[a], 1);
        g_src[q] = b; g_w[q] = w;
    }
}

// ---------------- fp32 -> fp16 convert of the node table (layer 1 only) ----------
__global__ void k_cvt(const float* __restrict__ x) {
    int i = blockIdx.x * blockDim.x + threadIdx.x;
    const int N4 = NN * DM / 4;
    if (i < N4) {
        float4 v = __ldg(&((const float4*)x)[i]);
        ((__half2*)g_xh)[2 * i]     = __floats2half2_rn(v.x, v.y);
        ((__half2*)g_xh)[2 * i + 1] = __floats2half2_rn(v.z, v.w);
    }
}

// ---------------- W^T fp16 prep (once per layer) ----------------
__global__ void k_prepW(const float* __restrict__ W) {
    int i = blockIdx.x * blockDim.x + threadIdx.x;   // i = k*128 + n (coalesced read)
    if (i < DM * DM) {
        int n = i & 127, k = i >> 7;
        g_wt[n * DM + k] = __float2half_rn(W[i]);
    }
}

// ---------------- aggregation: one warp per node, fp16 gather, MLP=4 -------------
__device__ __forceinline__ void acc_edge(float4& acc, float w, uint2 u) {
    __half2 h0 = *(__half2*)&u.x;
    __half2 h1 = *(__half2*)&u.y;
    float2 f0 = __half22float2(h0);
    float2 f1 = __half22float2(h1);
    acc.x = fmaf(w, f0.x, acc.x);
    acc.y = fmaf(w, f0.y, acc.y);
    acc.z = fmaf(w, f1.x, acc.z);
    acc.w = fmaf(w, f1.y, acc.w);
}

__global__ void k_agg() {
    int warp = (blockIdx.x * blockDim.x + threadIdx.x) >> 5;
    int lane = threadIdx.x & 31;
    if (warp >= NN) return;
    int beg = g_off[warp], end = g_off[warp + 1];
    float4 acc = make_float4(0.f, 0.f, 0.f, 0.f);
    const uint2* __restrict__ xh2 = (const uint2*)g_xh;

    int j = beg;
    for (; j + 4 <= end; j += 4) {
        int s0 = __ldg(&g_src[j + 0]);
        int s1 = __ldg(&g_src[j + 1]);
        int s2 = __ldg(&g_src[j + 2]);
        int s3 = __ldg(&g_src[j + 3]);
        float w0 = __ldg(&g_w[j + 0]);
        float w1 = __ldg(&g_w[j + 1]);
        float w2 = __ldg(&g_w[j + 2]);
        float w3 = __ldg(&g_w[j + 3]);
        uint2 u0 = __ldg(&xh2[(size_t)s0 * 32 + lane]);
        uint2 u1 = __ldg(&xh2[(size_t)s1 * 32 + lane]);
        uint2 u2 = __ldg(&xh2[(size_t)s2 * 32 + lane]);
        uint2 u3 = __ldg(&xh2[(size_t)s3 * 32 + lane]);
        acc_edge(acc, w0, u0);
        acc_edge(acc, w1, u1);
        acc_edge(acc, w2, u2);
        acc_edge(acc, w3, u3);
    }
    {
        int rem = end - j;
        int s0 = 0, s1 = 0, s2 = 0;
        float w0 = 0.f, w1 = 0.f, w2 = 0.f;
        if (rem > 0) { s0 = __ldg(&g_src[j + 0]); w0 = __ldg(&g_w[j + 0]); }
        if (rem > 1) { s1 = __ldg(&g_src[j + 1]); w1 = __ldg(&g_w[j + 1]); }
        if (rem > 2) { s2 = __ldg(&g_src[j + 2]); w2 = __ldg(&g_w[j + 2]); }
        uint2 z = make_uint2(0u, 0u);
        uint2 u0 = (rem > 0) ? __ldg(&xh2[(size_t)s0 * 32 + lane]) : z;
        uint2 u1 = (rem > 1) ? __ldg(&xh2[(size_t)s1 * 32 + lane]) : z;
        uint2 u2 = (rem > 2) ? __ldg(&xh2[(size_t)s2 * 32 + lane]) : z;
        acc_edge(acc, w0, u0);
        acc_edge(acc, w1, u1);
        acc_edge(acc, w2, u2);
    }
    // write fp16 directly (A operand of the HMMA GEMM)
    uint2 hv;
    hv.x = h2_to_u32(__floats2half2_rn(acc.x, acc.y));
    hv.y = h2_to_u32(__floats2half2_rn(acc.z, acc.w));
    ((uint2*)g_aggh)[(size_t)warp * 32 + lane] = hv;
}

// ---------------- HMMA GEMM: out = res + g_aggh @ W + b --------------------------
// 128x128 tile per CTA, 8 warps; warp w -> rows [16w,16w+16), all 128 cols.
// A, B(W^T) fp16 in smem stride 136 halves (272B: conflict-free ldmatrix).
#define SAW 136

__global__ void __launch_bounds__(256)
k_gemm_mma(const float* __restrict__ bias, const float* __restrict__ res,
           float* __restrict__ out, int write_half) {
    extern __shared__ __half sh[];
    __half* sA = sh;                         // [128][SAW]
    __half* sB = sh + 128 * SAW;             // [128][SAW]  (W^T: [n][k])
    float* sBias = (float*)(sh + 2 * 128 * SAW);

    int tid = threadIdx.x;
    int w = tid >> 5, l = tid & 31;
    int rowBase = blockIdx.x * 128;

    if (tid < 128) sBias[tid] = __ldg(&bias[tid]);

    // load A tile from g_aggh (128 rows x 64 half2)
    const __half2* ag = (const __half2*)g_aggh;
#pragma unroll
    for (int i = 0; i < 32; i++) {
        int idx = tid + i * 256;             // 0..8191
        int row = idx >> 6;
        int kk = idx & 63;                   // half2 index along k
        int grow = rowBase + row;
        __half2 v = (grow < NN) ? __ldg(&ag[(size_t)grow * 64 + kk])
                                : __float2half2_rn(0.f);
        *(__half2*)&sA[row * SAW + kk * 2] = v;
    }
    // load B = W^T [n][k]
    const __half2* wt = (const __half2*)g_wt;
#pragma unroll
    for (int i = 0; i < 32; i++) {
        int idx = tid + i * 256;
        int n = idx >> 6;
        int kk = idx & 63;
        *(__half2*)&sB[n * SAW + kk * 2] = __ldg(&wt[idx]);
    }
    __syncthreads();

    uint32_t aBase = smem_to_u32(sA);
    uint32_t bBase = smem_to_u32(sB);

    float acc[16][4];
#pragma unroll
    for (int i = 0; i < 16; i++)
#pragma unroll
        for (int jj = 0; jj < 4; jj++) acc[i][jj] = 0.f;

    // lane address components (constant over k loop)
    int aRow = 16 * w + (l & 15);
    int aKsub = (l >> 4) * 8;                // 0 or 8
    int bNsub = ((l >> 4) & 1) * 8 + (l & 7);
    int bKsub = ((l >> 3) & 1) * 8;

#pragma unroll
    for (int s = 0; s < 8; s++) {
        uint32_t a[4];
        ldsm4(a, aBase + ((aRow * SAW + s * 16 + aKsub) << 1));
#pragma unroll
        for (int ntp = 0; ntp < 8; ntp++) {
            uint32_t b[4];
            int n = 16 * ntp + bNsub;
            ldsm4(b, bBase + ((n * SAW + s * 16 + bKsub) << 1));
            mma16816(acc[2 * ntp + 0], a, b);
            mma16816(acc[2 * ntp + 1], a, b + 2);
        }
    }

    // epilogue: + residual + bias; fp32 out (+ optional fp16 copy)
    int group = l >> 2, tg = l & 3;
#pragma unroll
    for (int hh = 0; hh < 2; hh++) {
        int grow = rowBase + 16 * w + group + hh * 8;
        if (grow < NN) {
            const float* rp = &res[(size_t)grow * DM];
            float* op = &out[(size_t)grow * DM];
            __half* hp = &g_xh[(size_t)grow * DM];
#pragma unroll
            for (int nt = 0; nt < 16; nt++) {
                int c = 8 * nt + 2 * tg;
                float2 rv = *(const float2*)&rp[c];
                float o0 = rv.x + acc[nt][hh * 2 + 0] + sBias[c];
                float o1 = rv.y + acc[nt][hh * 2 + 1] + sBias[c + 1];
                *(float2*)&op[c] = make_float2(o0, o1);
                if (write_half)
                    *(uint32_t*)&hp[c] = h2_to_u32(__floats2half2_rn(o0, o1));
            }
        }
    }
}

// ---------------- launch ----------------
extern "C" void kernel_launch(void* const* d_in, const int* in_sizes, int n_in,
                              void* d_out, int out_size) {
    const float* nodes     = (const float*)d_in[0];
    const int*   senders   = (const int*)d_in[1];
    const int*   receivers = (const int*)d_in[2];
    const float* edges     = (const float*)d_in[3];
    const float* W1 = (const float*)d_in[4];
    const float* b1 = (const float*)d_in[5];
    const float* W2 = (const float*)d_in[6];
    const float* b2 = (const float*)d_in[7];
    float* out = (float*)d_out;

    float* buf1 = nullptr;
    cudaGetSymbolAddress((void**)&buf1, g_buf1);

    const size_t SMEM_GEMM = 2 * 128 * SAW * sizeof(__half) + DM * sizeof(float);
    cudaFuncSetAttribute(k_gemm_mma, cudaFuncAttributeMaxDynamicSharedMemorySize,
                         (int)SMEM_GEMM);

    const int T = 256;
    // CSR + degree build (shared by both layers)
    k_zero<<<(NN + T - 1) / T, T>>>();
    k_deg<<<(NE + T - 1) / T, T>>>(senders, receivers, edges);
    k_dis<<<(NN + T - 1) / T, T>>>();
    k_scan1<<<SNB, SCB>>>();
    k_scan2<<<1, 512>>>();
    k_scan3<<<SNB, SCB>>>();
    k_fill<<<(NE + T - 1) / T, T>>>(senders, receivers, edges);

    const int AGG_GRID  = (NN * 32 + T - 1) / T;       // one warp per node
    const int GEMM_GRID = (NN + 127) / 128;            // 782 tiles
    const int CVT_GRID  = (NN * DM / 4 + T - 1) / T;

    // layer 1: nodes -> buf1 (gemm also emits fp16 copy for layer-2 gather)
    k_cvt<<<CVT_GRID, T>>>(nodes);
    k_prepW<<<(DM * DM + T - 1) / T, T>>>(W1);
    k_agg<<<AGG_GRID, T>>>();
    k_gemm_mma<<<GEMM_GRID, T, SMEM_GEMM>>>(b1, nodes, buf1, 1);

    // layer 2: buf1 -> out
    k_prepW<<<(DM * DM + T - 1) / T, T>>>(W2);
    k_agg<<<AGG_GRID, T>>>();
    k_gemm_mma<<<GEMM_GRID, T, SMEM_GEMM>>>(b2, buf1, out, 0);
}